// round 16
// baseline (speedup 1.0000x reference)
#include <cuda_runtime.h>
#include <cuda_bf16.h>
#include <cstdint>
#include <math.h>

#define BB 64
#define LL 2048
#define DD 256
#define KK 32
#define NCHUNK 2
#define CHUNK 1024
#define ST 128
#define NSUB 8
#define NTH 128

// bf16 element strides (padded -> ldmatrix phases conflict-free)
#define XSTR 264            // 528 B row stride (132 words = 4 mod 32)
#define WSTR 264
#define PSTR 40             // 80 B (20 words mod 32)

// smem byte offsets
#define XHI 0               // [128][264] bf16 = 67584 B
#define XLO 67584
#define WSM 135168          // [64][264] bf16: rows 0-31 Whi, 32-63 Wlo
#define PHI 168960          // [128][40] bf16
#define PLO 179200
#define SSUM 189440         // 32 floats
#define SMEM_BYTES (SSUM + 256)

__device__ float g_partC[BB * NCHUNK * KK * DD];   // 4 MB
__device__ float g_partS[BB * NCHUNK * KK];
__device__ int   g_flag[BB];                        // zero-init; self-resetting

__device__ __forceinline__ uint32_t s2u(const void* p) {
    uint32_t a;
    asm("{ .reg .u64 t; cvta.to.shared.u64 t, %1; cvt.u32.u64 %0, t; }" : "=r"(a) : "l"(p));
    return a;
}
// truncation split helpers: hi = top 16 bits (exact bf16), lo = f - hi
__device__ __forceinline__ float trunchi(float f) {
    return __uint_as_float(__float_as_uint(f) & 0xFFFF0000u);
}
__device__ __forceinline__ uint32_t hipack(float a, float b) {   // pk(bf16(a_hi), bf16(b_hi))
    return __byte_perm(__float_as_uint(a), __float_as_uint(b), 0x7632);
}
__device__ __forceinline__ uint32_t lopack(float lo0, float lo1) { // pk(bf16(lo0), bf16(lo1))
    uint32_t r;
    asm("cvt.rn.bf16x2.f32 %0, %1, %2;" : "=r"(r) : "f"(lo1), "f"(lo0));
    return r;
}

#define LDSM4(r, a) \
    asm volatile("ldmatrix.sync.aligned.m8n8.x4.shared.b16 {%0,%1,%2,%3}, [%4];" \
        : "=r"((r)[0]), "=r"((r)[1]), "=r"((r)[2]), "=r"((r)[3]) : "r"(a))
#define LDSM4T(r, a) \
    asm volatile("ldmatrix.sync.aligned.m8n8.x4.trans.shared.b16 {%0,%1,%2,%3}, [%4];" \
        : "=r"((r)[0]), "=r"((r)[1]), "=r"((r)[2]), "=r"((r)[3]) : "r"(a))
#define MMA(c, a, b0, b1) \
    asm volatile("mma.sync.aligned.m16n8k16.row.col.f32.bf16.bf16.f32 " \
        "{%0,%1,%2,%3}, {%4,%5,%6,%7}, {%8,%9}, {%0,%1,%2,%3};" \
        : "+f"((c)[0]), "+f"((c)[1]), "+f"((c)[2]), "+f"((c)[3]) \
        : "r"((a)[0]), "r"((a)[1]), "r"((a)[2]), "r"((a)[3]), "r"(b0), "r"(b1))

__global__ __launch_bounds__(NTH, 1)
void fused_kernel(const float* __restrict__ X, const float* __restrict__ W,
                  float* __restrict__ out) {
    extern __shared__ __align__(128) char smem[];
    const uint32_t sb = s2u(smem);
    float* Ssum = (float*)(smem + SSUM);
    __shared__ int s_winner;

    const int t = threadIdx.x, lane = t & 31, w = t >> 5;     // 4 warps
    const int g = lane >> 2, tid4 = lane & 3;
    const int cchunk = blockIdx.x, b = blockIdx.y;

    // ---- W -> Whi/Wlo (truncation split), once ----
    for (int i = t; i < KK * DD; i += NTH) {
        int k = i >> 8, d = i & 255;
        float v = W[i];
        float hi = trunchi(v);
        *(uint16_t*)(smem + WSM + (k * WSTR + d) * 2)        = (uint16_t)(__float_as_uint(v) >> 16);
        *(uint16_t*)(smem + WSM + ((k + 32) * WSTR + d) * 2) = (uint16_t)(lopack(v - hi, 0.f) & 0xFFFFu);
    }
    if (t < KK) Ssum[t] = 0.f;

    // ---- per-thread ldmatrix address components ----
    // GEMM1 A (X rows, non-trans x4): warp rows 32w + 16*mt + ...
    const uint32_t a1_lane = (uint32_t)(((lane & 7) + ((lane >> 3) & 1) * 8) * (XSTR * 2)
                                        + ((lane >> 4) & 1) * 16);
    const uint32_t a1_base0 = (uint32_t)((w * 32) * (XSTR * 2)) + a1_lane;
    const uint32_t a1_base1 = a1_base0 + (uint32_t)(16 * XSTR * 2);
    // GEMM1 W (non-trans x4, 4 nt matrices): lane -> row (lane>>3)*8 + (lane&7)
    const uint32_t w_off = (uint32_t)((((lane >> 3) * 8) + (lane & 7)) * (WSTR * 2));
    // GEMM2 A (X^T via trans x4): d-range 64w
    const uint32_t a2_row = (uint32_t)((lane & 7) + ((lane >> 4) & 1) * 8);
    const uint32_t a2_colb = (uint32_t)((w * 64 + ((lane >> 3) & 1) * 8) * 2);
    // GEMM2 B (P^T via trans x4)
    const uint32_t b2_row = (uint32_t)((lane & 7) + ((lane >> 3) & 1) * 8);
    const uint32_t b2_colb = (uint32_t)(((lane >> 4) & 1) * 16);

    float Cacc[4][4][4];
    #pragma unroll
    for (int m = 0; m < 4; m++)
        #pragma unroll
        for (int n = 0; n < 4; n++)
            #pragma unroll
            for (int j = 0; j < 4; j++) Cacc[m][n][j] = 0.f;
    float Sacc[8];
    #pragma unroll
    for (int i = 0; i < 8; i++) Sacc[i] = 0.f;

    const float* Xg = X + ((size_t)b * LL + (size_t)cchunk * CHUNK) * DD;

    // prologue prefetch: rows 0-31 of subtile 0
    float4 pf[16];
    {
        const float4* ns = (const float4*)Xg;
        #pragma unroll
        for (int j = 0; j < 16; j++)
            pf[j] = ns[((size_t)(j >> 1) * 128 + t) * 2 + (j & 1)];
    }

    for (int sub = 0; sub < NSUB; sub++) {
        // ---- stage X subtile: f32 -> Xhi/Xlo bf16 (truncation split) ----
        {
            const float4* src = (const float4*)(Xg + (size_t)sub * ST * DD);
            #pragma unroll
            for (int it = 0; it < 32; it++) {
                const int idx = it * NTH + t;
                float4 v0, v1;
                if (it < 8) { v0 = pf[it * 2]; v1 = pf[it * 2 + 1]; }
                else        { v0 = src[idx * 2]; v1 = src[idx * 2 + 1]; }
                const int row = idx >> 5, cg = idx & 31;
                uint32_t h01 = hipack(v0.x, v0.y), h23 = hipack(v0.z, v0.w);
                uint32_t h45 = hipack(v1.x, v1.y), h67 = hipack(v1.z, v1.w);
                uint32_t l01 = lopack(v0.x - trunchi(v0.x), v0.y - trunchi(v0.y));
                uint32_t l23 = lopack(v0.z - trunchi(v0.z), v0.w - trunchi(v0.w));
                uint32_t l45 = lopack(v1.x - trunchi(v1.x), v1.y - trunchi(v1.y));
                uint32_t l67 = lopack(v1.z - trunchi(v1.z), v1.w - trunchi(v1.w));
                const uint32_t off = (uint32_t)(row * (XSTR * 2) + cg * 16);
                *(uint4*)(smem + XHI + off) = make_uint4(h01, h23, h45, h67);
                *(uint4*)(smem + XLO + off) = make_uint4(l01, l23, l45, l67);
            }
        }
        __syncthreads();

        // ---- GEMM1: D1[32 rows of warp][32 codes] = X @ W^T (3-term) ----
        float d1[2][4][4];
        #pragma unroll
        for (int m = 0; m < 2; m++)
            #pragma unroll
            for (int n = 0; n < 4; n++)
                #pragma unroll
                for (int j = 0; j < 4; j++) d1[m][n][j] = 0.f;
        #pragma unroll 4
        for (int ks = 0; ks < 16; ks++) {
            uint32_t wh0[4], wh1[4], wl0[4], wl1[4];
            const uint32_t wa = sb + WSM + w_off + ks * 32;
            LDSM4(wh0, wa);
            LDSM4(wh1, wa + 16);
            LDSM4(wl0, wa + 32 * (WSTR * 2));
            LDSM4(wl1, wa + 32 * (WSTR * 2) + 16);
            #pragma unroll
            for (int mt = 0; mt < 2; mt++) {
                uint32_t Ah[4], Al[4];
                const uint32_t xa = (mt ? a1_base1 : a1_base0) + ks * 32;
                LDSM4(Ah, sb + XHI + xa);
                LDSM4(Al, sb + XLO + xa);
                #pragma unroll
                for (int nt = 0; nt < 4; nt++) {
                    MMA(d1[mt][nt], Ah, wh0[nt], wh1[nt]);
                    MMA(d1[mt][nt], Ah, wl0[nt], wl1[nt]);
                    MMA(d1[mt][nt], Al, wh0[nt], wh1[nt]);
                }
            }
        }

        // ---- exp in registers; store P hi/lo [l][code]; accumulate S ----
        #pragma unroll
        for (int mt = 0; mt < 2; mt++) {
            const int r0 = w * 32 + mt * 16 + g, r1 = r0 + 8;
            #pragma unroll
            for (int nt = 0; nt < 4; nt++) {
                float p0 = __expf(d1[mt][nt][0]);
                float p1 = __expf(d1[mt][nt][1]);
                float p2 = __expf(d1[mt][nt][2]);
                float p3 = __expf(d1[mt][nt][3]);
                Sacc[nt * 2]     += p0 + p2;
                Sacc[nt * 2 + 1] += p1 + p3;
                const uint32_t o0 = (uint32_t)(r0 * (PSTR * 2) + (nt * 8 + 2 * tid4) * 2);
                const uint32_t o1 = (uint32_t)(r1 * (PSTR * 2) + (nt * 8 + 2 * tid4) * 2);
                *(uint32_t*)(smem + PHI + o0) = hipack(p0, p1);
                *(uint32_t*)(smem + PHI + o1) = hipack(p2, p3);
                *(uint32_t*)(smem + PLO + o0) = lopack(p0 - trunchi(p0), p1 - trunchi(p1));
                *(uint32_t*)(smem + PLO + o1) = lopack(p2 - trunchi(p2), p3 - trunchi(p3));
            }
        }
        __syncthreads();

        // prefetch next subtile rows 0-31 (lands during GEMM2)
        if (sub + 1 < NSUB) {
            const float4* ns = (const float4*)(Xg + (size_t)(sub + 1) * ST * DD);
            #pragma unroll
            for (int j = 0; j < 16; j++)
                pf[j] = ns[((size_t)(j >> 1) * 128 + t) * 2 + (j & 1)];
        }

        // ---- GEMM2: C^T[64 d of warp][32 codes] += X^T @ P^T (3-term) ----
        #pragma unroll
        for (int ks = 0; ks < 8; ks++) {
            const int l0 = ks * 16;
            uint32_t BPh[8], BPl[8];
            const uint32_t pa = sb + PHI + (l0 + b2_row) * (PSTR * 2) + b2_colb;
            LDSM4T(BPh, pa);
            LDSM4T(BPh + 4, pa + 32);
            const uint32_t pl = sb + PLO + (l0 + b2_row) * (PSTR * 2) + b2_colb;
            LDSM4T(BPl, pl);
            LDSM4T(BPl + 4, pl + 32);
            #pragma unroll
            for (int mt = 0; mt < 4; mt++) {
                uint32_t Ah[4], Al[4];
                const uint32_t xa = (l0 + a2_row) * (XSTR * 2) + a2_colb + mt * 32;
                LDSM4T(Ah, sb + XHI + xa);
                LDSM4T(Al, sb + XLO + xa);
                #pragma unroll
                for (int nt = 0; nt < 4; nt++) {
                    MMA(Cacc[mt][nt], Ah, BPh[nt * 2], BPh[nt * 2 + 1]);
                    MMA(Cacc[mt][nt], Ah, BPl[nt * 2], BPl[nt * 2 + 1]);
                    MMA(Cacc[mt][nt], Al, BPh[nt * 2], BPh[nt * 2 + 1]);
                }
            }
        }
        __syncthreads();   // X/P free for next subtile
    }

    // ---- softmax denominators: reduce over row-lanes, atomic into Ssum ----
    #pragma unroll
    for (int i = 0; i < 8; i++) {
        float v = Sacc[i];
        v += __shfl_xor_sync(0xffffffffu, v, 4);
        v += __shfl_xor_sync(0xffffffffu, v, 8);
        v += __shfl_xor_sync(0xffffffffu, v, 16);
        Sacc[i] = v;
    }
    if (lane < 4) {
        #pragma unroll
        for (int nt = 0; nt < 4; nt++) {
            atomicAdd(&Ssum[nt * 8 + 2 * lane],     Sacc[nt * 2]);
            atomicAdd(&Ssum[nt * 8 + 2 * lane + 1], Sacc[nt * 2 + 1]);
        }
    }
    __syncthreads();

    // ---- write partials ----
    const int bc = b * NCHUNK + cchunk;
    float* Co = g_partC + (size_t)bc * KK * DD;
    #pragma unroll
    for (int mt = 0; mt < 4; mt++) {
        const int dr = w * 64 + mt * 16 + g;
        #pragma unroll
        for (int nt = 0; nt < 4; nt++) {
            const int c0 = nt * 8 + 2 * tid4;
            Co[(size_t)c0 * DD + dr]           = Cacc[mt][nt][0];
            Co[(size_t)(c0 + 1) * DD + dr]     = Cacc[mt][nt][1];
            Co[(size_t)c0 * DD + dr + 8]       = Cacc[mt][nt][2];
            Co[(size_t)(c0 + 1) * DD + dr + 8] = Cacc[mt][nt][3];
        }
    }
    if (t < KK) g_partS[bc * KK + t] = Ssum[t];

    // ---- last-CTA-per-batch combine (fence + atomic flag, self-resetting) ----
    __threadfence();
    __syncthreads();
    if (t == 0) s_winner = (atomicAdd(&g_flag[b], 1) == 1);
    __syncthreads();
    if (s_winner) {
        __threadfence();
        const float* S0 = g_partS + (size_t)(b * NCHUNK) * KK;
        const float* S1 = S0 + KK;
        if (t < KK) Ssum[t] = 1.f / (S0[t] + S1[t]);
        __syncthreads();
        const float4* C0 = (const float4*)(g_partC + (size_t)(b * NCHUNK) * KK * DD);
        const float4* C1 = (const float4*)(g_partC + (size_t)(b * NCHUNK + 1) * KK * DD);
        float4* O = (float4*)(out + (size_t)b * KK * DD);
        #pragma unroll
        for (int i = 0; i < 16; i++) {
            const int idx = i * NTH + t;          // 2048 float4s
            const int k = idx >> 6;
            float inv = Ssum[k];
            float4 a = C0[idx], c = C1[idx];
            O[idx] = make_float4((a.x + c.x) * inv, (a.y + c.y) * inv,
                                 (a.z + c.z) * inv, (a.w + c.w) * inv);
        }
        if (t == 0) g_flag[b] = 0;                // reset for next launch/replay
    }
}

extern "C" void kernel_launch(void* const* d_in, const int* in_sizes, int n_in,
                              void* d_out, int out_size) {
    const float* X = (const float*)d_in[0];   // rev_repr (64, 2048, 256) f32
    const float* W = (const float*)d_in[1];   // W_codes  (32, 256) f32
    float* out = (float*)d_out;               // contexts (64, 32, 256) f32

    cudaFuncSetAttribute(fused_kernel, cudaFuncAttributeMaxDynamicSharedMemorySize, SMEM_BYTES);
    dim3 grid(NCHUNK, BB);
    fused_kernel<<<grid, NTH, SMEM_BYTES>>>(X, W, out);
}

// round 17
// speedup vs baseline: 1.2134x; 1.2134x over previous
#include <cuda_runtime.h>
#include <cuda_bf16.h>
#include <cstdint>
#include <math.h>

#define BB 64
#define LL 2048
#define DD 256
#define KK 32
#define NCHUNK 2
#define CHUNK 1024
#define ST 128
#define NSUB 8
#define NTH 256

// bf16 element strides (padded -> ldmatrix phases conflict-free)
#define XSTR 264            // 528 B row stride (132 words = 4 mod 32)
#define WSTR 264
#define PSTR 40             // 80 B (20 words mod 32)

// smem byte offsets
#define XHI 0               // [128][264] bf16 = 67584 B
#define XLO 67584
#define WSM 135168          // [64][264] bf16: rows 0-31 Whi, 32-63 Wlo
#define PHI 168960          // [128][40] bf16
#define PLO 179200
#define SSUM 189440         // 32 floats
#define SMEM_BYTES (SSUM + 256)

__device__ float g_partC[BB * NCHUNK * KK * DD];   // 4 MB
__device__ float g_partS[BB * NCHUNK * KK];
__device__ int   g_flag[BB];                        // zero-init; self-resetting

__device__ __forceinline__ uint32_t s2u(const void* p) {
    uint32_t a;
    asm("{ .reg .u64 t; cvta.to.shared.u64 t, %1; cvt.u32.u64 %0, t; }" : "=r"(a) : "l"(p));
    return a;
}
// truncation split: hi = top 16 bits (exact bf16), lo = f - hi
__device__ __forceinline__ float trunchi(float f) {
    return __uint_as_float(__float_as_uint(f) & 0xFFFF0000u);
}
__device__ __forceinline__ uint32_t hipack(float a, float b) {
    return __byte_perm(__float_as_uint(a), __float_as_uint(b), 0x7632);
}
__device__ __forceinline__ uint32_t lopack(float lo0, float lo1) {
    uint32_t r;
    asm("cvt.rn.bf16x2.f32 %0, %1, %2;" : "=r"(r) : "f"(lo1), "f"(lo0));
    return r;
}

#define LDSM4(r, a) \
    asm volatile("ldmatrix.sync.aligned.m8n8.x4.shared.b16 {%0,%1,%2,%3}, [%4];" \
        : "=r"((r)[0]), "=r"((r)[1]), "=r"((r)[2]), "=r"((r)[3]) : "r"(a))
#define LDSM4T(r, a) \
    asm volatile("ldmatrix.sync.aligned.m8n8.x4.trans.shared.b16 {%0,%1,%2,%3}, [%4];" \
        : "=r"((r)[0]), "=r"((r)[1]), "=r"((r)[2]), "=r"((r)[3]) : "r"(a))
#define MMA(c, a, b0, b1) \
    asm volatile("mma.sync.aligned.m16n8k16.row.col.f32.bf16.bf16.f32 " \
        "{%0,%1,%2,%3}, {%4,%5,%6,%7}, {%8,%9}, {%0,%1,%2,%3};" \
        : "+f"((c)[0]), "+f"((c)[1]), "+f"((c)[2]), "+f"((c)[3]) \
        : "r"((a)[0]), "r"((a)[1]), "r"((a)[2]), "r"((a)[3]), "r"(b0), "r"(b1))

__global__ __launch_bounds__(NTH, 1)
void fused_kernel(const float* __restrict__ X, const float* __restrict__ W,
                  float* __restrict__ out) {
    extern __shared__ __align__(128) char smem[];
    const uint32_t sb = s2u(smem);
    float* Ssum = (float*)(smem + SSUM);
    __shared__ int s_winner;

    const int t = threadIdx.x, lane = t & 31, w = t >> 5;     // 8 warps
    const int g = lane >> 2, tid4 = lane & 3;
    const int cchunk = blockIdx.x, b = blockIdx.y;

    // ---- W -> Whi/Wlo (truncation split), once ----
    for (int i = t; i < KK * DD; i += NTH) {
        int k = i >> 8, d = i & 255;
        float v = W[i];
        float hi = trunchi(v);
        *(uint16_t*)(smem + WSM + (k * WSTR + d) * 2)        = (uint16_t)(__float_as_uint(v) >> 16);
        *(uint16_t*)(smem + WSM + ((k + 32) * WSTR + d) * 2) = (uint16_t)(lopack(v - hi, 0.f) & 0xFFFFu);
    }
    if (t < KK) Ssum[t] = 0.f;

    // ---- per-thread ldmatrix address components ----
    // GEMM1 A (X rows 16w..16w+15, non-trans x4)
    const uint32_t a1_off = (uint32_t)((w * 16 + (lane & 7) + ((lane >> 3) & 1) * 8) * (XSTR * 2)
                                       + ((lane >> 4) & 1) * 16);
    // GEMM1 W (consolidated non-trans x4): lane L -> row L (m0=rows0-7,...,m3=rows24-31)
    const uint32_t w_off = (uint32_t)((((lane >> 3) * 8) + (lane & 7)) * (WSTR * 2));
    // GEMM2 A (X^T via trans x4): d-range 32w
    const uint32_t a2_row = (uint32_t)((lane & 7) + ((lane >> 4) & 1) * 8);
    const uint32_t a2_colb = (uint32_t)((w * 32 + ((lane >> 3) & 1) * 8) * 2);
    // GEMM2 B (P^T via trans x4)
    const uint32_t b2_row = (uint32_t)((lane & 7) + ((lane >> 3) & 1) * 8);
    const uint32_t b2_colb = (uint32_t)(((lane >> 4) & 1) * 16);

    float Cacc[2][4][4];
    #pragma unroll
    for (int m = 0; m < 2; m++)
        #pragma unroll
        for (int n = 0; n < 4; n++)
            #pragma unroll
            for (int j = 0; j < 4; j++) Cacc[m][n][j] = 0.f;
    float Sacc[8];
    #pragma unroll
    for (int i = 0; i < 8; i++) Sacc[i] = 0.f;

    const float* Xg = X + ((size_t)b * LL + (size_t)cchunk * CHUNK) * DD;

    // prologue prefetch: first 8 float4 groups of subtile 0 (it = 0..3)
    float4 pf[8];
    {
        const float4* ns = (const float4*)Xg;
        #pragma unroll
        for (int j = 0; j < 8; j++)
            pf[j] = ns[((size_t)(j >> 1) * NTH + t) * 2 + (j & 1)];
    }

    for (int sub = 0; sub < NSUB; sub++) {
        // ---- stage X subtile: f32 -> Xhi/Xlo bf16 (truncation split) ----
        {
            const float4* src = (const float4*)(Xg + (size_t)sub * ST * DD);
            #pragma unroll
            for (int it = 0; it < 16; it++) {
                const int idx = it * NTH + t;        // 4096 pairs of float4
                float4 v0, v1;
                if (it < 4) { v0 = pf[it * 2]; v1 = pf[it * 2 + 1]; }
                else        { v0 = src[idx * 2]; v1 = src[idx * 2 + 1]; }
                const int row = idx >> 5, cg = idx & 31;
                uint32_t h01 = hipack(v0.x, v0.y), h23 = hipack(v0.z, v0.w);
                uint32_t h45 = hipack(v1.x, v1.y), h67 = hipack(v1.z, v1.w);
                uint32_t l01 = lopack(v0.x - trunchi(v0.x), v0.y - trunchi(v0.y));
                uint32_t l23 = lopack(v0.z - trunchi(v0.z), v0.w - trunchi(v0.w));
                uint32_t l45 = lopack(v1.x - trunchi(v1.x), v1.y - trunchi(v1.y));
                uint32_t l67 = lopack(v1.z - trunchi(v1.z), v1.w - trunchi(v1.w));
                const uint32_t off = (uint32_t)(row * (XSTR * 2) + cg * 16);
                *(uint4*)(smem + XHI + off) = make_uint4(h01, h23, h45, h67);
                *(uint4*)(smem + XLO + off) = make_uint4(l01, l23, l45, l67);
            }
        }
        __syncthreads();

        // ---- GEMM1: D1[16 rows of warp][32 codes] = X @ W^T (3-term) ----
        float d1[4][4];
        #pragma unroll
        for (int n = 0; n < 4; n++)
            #pragma unroll
            for (int j = 0; j < 4; j++) d1[n][j] = 0.f;
        #pragma unroll 4
        for (int ks = 0; ks < 16; ks++) {
            uint32_t wh0[4], wh1[4], wl0[4], wl1[4];
            const uint32_t wa = sb + WSM + w_off + ks * 32;
            LDSM4(wh0, wa);
            LDSM4(wh1, wa + 16);
            LDSM4(wl0, wa + 32 * (WSTR * 2));
            LDSM4(wl1, wa + 32 * (WSTR * 2) + 16);
            uint32_t Ah[4], Al[4];
            const uint32_t xa = a1_off + ks * 32;
            LDSM4(Ah, sb + XHI + xa);
            LDSM4(Al, sb + XLO + xa);
            #pragma unroll
            for (int nt = 0; nt < 4; nt++) {
                MMA(d1[nt], Ah, wh0[nt], wh1[nt]);
                MMA(d1[nt], Ah, wl0[nt], wl1[nt]);
                MMA(d1[nt], Al, wh0[nt], wh1[nt]);
            }
        }

        // ---- exp in registers; store P hi/lo [l][code]; accumulate S ----
        {
            const int r0 = w * 16 + g, r1 = r0 + 8;
            #pragma unroll
            for (int nt = 0; nt < 4; nt++) {
                float p0 = __expf(d1[nt][0]);
                float p1 = __expf(d1[nt][1]);
                float p2 = __expf(d1[nt][2]);
                float p3 = __expf(d1[nt][3]);
                Sacc[nt * 2]     += p0 + p2;
                Sacc[nt * 2 + 1] += p1 + p3;
                const uint32_t o0 = (uint32_t)(r0 * (PSTR * 2) + (nt * 8 + 2 * tid4) * 2);
                const uint32_t o1 = (uint32_t)(r1 * (PSTR * 2) + (nt * 8 + 2 * tid4) * 2);
                *(uint32_t*)(smem + PHI + o0) = hipack(p0, p1);
                *(uint32_t*)(smem + PHI + o1) = hipack(p2, p3);
                *(uint32_t*)(smem + PLO + o0) = lopack(p0 - trunchi(p0), p1 - trunchi(p1));
                *(uint32_t*)(smem + PLO + o1) = lopack(p2 - trunchi(p2), p3 - trunchi(p3));
            }
        }
        __syncthreads();

        // prefetch next subtile (lands during GEMM2)
        if (sub + 1 < NSUB) {
            const float4* ns = (const float4*)(Xg + (size_t)(sub + 1) * ST * DD);
            #pragma unroll
            for (int j = 0; j < 8; j++)
                pf[j] = ns[((size_t)(j >> 1) * NTH + t) * 2 + (j & 1)];
        }

        // ---- GEMM2: C^T[32 d of warp][32 codes] += X^T @ P^T (3-term) ----
        #pragma unroll
        for (int ks = 0; ks < 8; ks++) {
            const int l0 = ks * 16;
            uint32_t BPh[8], BPl[8];
            const uint32_t pa = sb + PHI + (l0 + b2_row) * (PSTR * 2) + b2_colb;
            LDSM4T(BPh, pa);
            LDSM4T(BPh + 4, pa + 32);
            const uint32_t pl = sb + PLO + (l0 + b2_row) * (PSTR * 2) + b2_colb;
            LDSM4T(BPl, pl);
            LDSM4T(BPl + 4, pl + 32);
            #pragma unroll
            for (int mt = 0; mt < 2; mt++) {
                uint32_t Ah[4], Al[4];
                const uint32_t xa = (l0 + a2_row) * (XSTR * 2) + a2_colb + mt * 32;
                LDSM4T(Ah, sb + XHI + xa);
                LDSM4T(Al, sb + XLO + xa);
                #pragma unroll
                for (int nt = 0; nt < 4; nt++) {
                    MMA(Cacc[mt][nt], Ah, BPh[nt * 2], BPh[nt * 2 + 1]);
                    MMA(Cacc[mt][nt], Ah, BPl[nt * 2], BPl[nt * 2 + 1]);
                    MMA(Cacc[mt][nt], Al, BPh[nt * 2], BPh[nt * 2 + 1]);
                }
            }
        }
        __syncthreads();   // X/P free for next subtile
    }

    // ---- softmax denominators: reduce over row-lanes, atomic into Ssum ----
    #pragma unroll
    for (int i = 0; i < 8; i++) {
        float v = Sacc[i];
        v += __shfl_xor_sync(0xffffffffu, v, 4);
        v += __shfl_xor_sync(0xffffffffu, v, 8);
        v += __shfl_xor_sync(0xffffffffu, v, 16);
        Sacc[i] = v;
    }
    if (lane < 4) {
        #pragma unroll
        for (int nt = 0; nt < 4; nt++) {
            atomicAdd(&Ssum[nt * 8 + 2 * lane],     Sacc[nt * 2]);
            atomicAdd(&Ssum[nt * 8 + 2 * lane + 1], Sacc[nt * 2 + 1]);
        }
    }
    __syncthreads();

    // ---- write partials ----
    const int bc = b * NCHUNK + cchunk;
    float* Co = g_partC + (size_t)bc * KK * DD;
    #pragma unroll
    for (int mt = 0; mt < 2; mt++) {
        const int dr = w * 32 + mt * 16 + g;
        #pragma unroll
        for (int nt = 0; nt < 4; nt++) {
            const int c0 = nt * 8 + 2 * tid4;
            Co[(size_t)c0 * DD + dr]           = Cacc[mt][nt][0];
            Co[(size_t)(c0 + 1) * DD + dr]     = Cacc[mt][nt][1];
            Co[(size_t)c0 * DD + dr + 8]       = Cacc[mt][nt][2];
            Co[(size_t)(c0 + 1) * DD + dr + 8] = Cacc[mt][nt][3];
        }
    }
    if (t < KK) g_partS[bc * KK + t] = Ssum[t];

    // ---- last-CTA-per-batch combine (fence + atomic flag, self-resetting) ----
    __threadfence();
    __syncthreads();
    if (t == 0) s_winner = (atomicAdd(&g_flag[b], 1) == 1);
    __syncthreads();
    if (s_winner) {
        __threadfence();
        const float* S0 = g_partS + (size_t)(b * NCHUNK) * KK;
        const float* S1 = S0 + KK;
        if (t < KK) Ssum[t] = 1.f / (S0[t] + S1[t]);
        __syncthreads();
        const float4* C0 = (const float4*)(g_partC + (size_t)(b * NCHUNK) * KK * DD);
        const float4* C1 = (const float4*)(g_partC + (size_t)(b * NCHUNK + 1) * KK * DD);
        float4* O = (float4*)(out + (size_t)b * KK * DD);
        #pragma unroll
        for (int i = 0; i < 8; i++) {
            const int idx = i * NTH + t;          // 2048 float4s
            const int k = idx >> 6;
            float inv = Ssum[k];
            float4 a = C0[idx], c = C1[idx];
            O[idx] = make_float4((a.x + c.x) * inv, (a.y + c.y) * inv,
                                 (a.z + c.z) * inv, (a.w + c.w) * inv);
        }
        if (t == 0) g_flag[b] = 0;                // reset for next launch/replay
    }
}

extern "C" void kernel_launch(void* const* d_in, const int* in_sizes, int n_in,
                              void* d_out, int out_size) {
    const float* X = (const float*)d_in[0];   // rev_repr (64, 2048, 256) f32
    const float* W = (const float*)d_in[1];   // W_codes  (32, 256) f32
    float* out = (float*)d_out;               // contexts (64, 32, 256) f32

    cudaFuncSetAttribute(fused_kernel, cudaFuncAttributeMaxDynamicSharedMemorySize, SMEM_BYTES);
    dim3 grid(NCHUNK, BB);
    fused_kernel<<<grid, NTH, SMEM_BYTES>>>(X, W, out);
}